// round 1
// baseline (speedup 1.0000x reference)
#include <cuda_runtime.h>

// VectorQuantizerEMA on GB300 (sm_103a)
// z: [16, 256, 4096] f32, codebook: [1024, 256] f32 -> out [16, 256, 4096] f32
// Fused fp32 distance-GEMM (packed fma.rn.f32x2) + argmin + gather.

#define NB    16
#define DDIM  256
#define TLEN  4096
#define KCB   1024
#define TM    128   // tokens per block
#define TKC   128   // codes per chunk
#define DSUB  32    // d-slice per cs tile
#define NTHR  256
#define NTILES 64   // 8 code chunks * 8 d-slices
#define CS_STRIDE 128
#define SMEM_FLOATS 45440   // 181760 bytes

__device__ float g_csq[KCB];

__global__ void csq_kernel(const float* __restrict__ cb) {
    int wid = threadIdx.x >> 5, lane = threadIdx.x & 31;
    int code = blockIdx.x * 8 + wid;
    const float* row = cb + (size_t)code * DDIM;
    float s = 0.f;
    #pragma unroll
    for (int d = 0; d < DDIM; d += 32) { float v = row[d + lane]; s = fmaf(v, v, s); }
    #pragma unroll
    for (int o = 16; o; o >>= 1) s += __shfl_xor_sync(0xffffffffu, s, o);
    if (lane == 0) g_csq[code] = s;
}

__device__ __forceinline__ unsigned long long pk2(float x) {
    unsigned long long r;
    asm("mov.b64 %0, {%1, %1};" : "=l"(r) : "f"(x));
    return r;
}

__device__ __forceinline__ void fma2(unsigned long long& d, unsigned long long a,
                                     unsigned long long b) {
    asm("fma.rn.f32x2 %0, %1, %2, %0;" : "+l"(d) : "l"(a), "l"(b));
}

__device__ __forceinline__ void upk(unsigned long long v, float& lo, float& hi) {
    asm("mov.b64 {%0, %1}, %2;" : "=f"(lo), "=f"(hi) : "l"(v));
}

__global__ __launch_bounds__(NTHR, 1)
void vq_kernel(const float* __restrict__ z, const float* __restrict__ cb,
               float* __restrict__ out) {
    extern __shared__ float sm[];
    float* zs    = sm;                     // 32896 floats (compute uses 32768; gather uses 128*257)
    float* cs    = sm + 32896;             // 2 * 32*128 = 8192 floats
    float* redv  = cs + 8192;              // 16*128
    int*   redi  = (int*)(redv + 2048);    // 16*128
    float* bestv = (float*)(redi + 2048);  // 128
    int*   besti = (int*)(bestv + 128);    // 128

    const int tid = threadIdx.x;
    const int tx  = tid & 15;              // token sub-block
    const int ty  = tid >> 4;              // code sub-block
    const int bid = blockIdx.x;
    const int batch = bid >> 5;
    const int t0 = (bid & 31) << 7;
    const float* zb = z + ((size_t)batch * DDIM) * TLEN + t0;

    if (tid < TM) { bestv[tid] = 3.4028235e38f; besti[tid] = 0; }

    // ---- load z tile: zs[d*128 + t], 8192 float4, coalesced ----
    #pragma unroll
    for (int r = 0; r < 32; r++) {
        int j  = tid + NTHR * r;
        int d  = j >> 5;
        int t4 = (j & 31) << 2;
        *(float4*)(zs + d * TM + t4) = *(const float4*)(zb + (size_t)d * TLEN + t4);
    }

    const int code0 = tid & 31;            // conflict-free transposed STS mapping
    const int dq0   = (tid >> 5) << 2;

    // ---- cs tile 0 (kc=0, ds=0) ----
    {
        #pragma unroll
        for (int s = 0; s < 4; s++) {
            int code = code0 + 32 * s;
            float4 v = *(const float4*)(cb + (size_t)code * DDIM + dq0);
            cs[(dq0 + 0) * CS_STRIDE + code] = v.x;
            cs[(dq0 + 1) * CS_STRIDE + code] = v.y;
            cs[(dq0 + 2) * CS_STRIDE + code] = v.z;
            cs[(dq0 + 3) * CS_STRIDE + code] = v.w;
        }
    }
    __syncthreads();

    unsigned long long acc[8][4];
    #pragma unroll
    for (int i = 0; i < 8; i++)
        #pragma unroll
        for (int j = 0; j < 4; j++) acc[i][j] = 0ull;

    for (int kc = 0; kc < 8; kc++) {
        for (int ds = 0; ds < 8; ds++) {
            const int t = kc * 8 + ds;
            const bool hasNext = (t + 1) < NTILES;
            float4 pf0, pf1, pf2, pf3;
            if (hasNext) {
                const int nt = t + 1;
                const int nkc = nt >> 3, nds = nt & 7;
                const float* gp = cb + (size_t)(nkc * TKC + code0) * DDIM + nds * DSUB + dq0;
                pf0 = *(const float4*)(gp);
                pf1 = *(const float4*)(gp + 32 * DDIM);
                pf2 = *(const float4*)(gp + 64 * DDIM);
                pf3 = *(const float4*)(gp + 96 * DDIM);
            }
            const float* cc = cs + (t & 1) * (DSUB * CS_STRIDE);
            const float* za = zs + ds * DSUB * TM + tx * 8;
            #pragma unroll 4
            for (int dd = 0; dd < DSUB; dd++) {
                float4 a0 = *(const float4*)(za + dd * TM);
                float4 a1 = *(const float4*)(za + dd * TM + 4);
                unsigned long long ap[8];
                ap[0] = pk2(a0.x); ap[1] = pk2(a0.y); ap[2] = pk2(a0.z); ap[3] = pk2(a0.w);
                ap[4] = pk2(a1.x); ap[5] = pk2(a1.y); ap[6] = pk2(a1.z); ap[7] = pk2(a1.w);
                const ulonglong2* bp = (const ulonglong2*)(cc + dd * CS_STRIDE + ty * 8);
                ulonglong2 bx = bp[0];
                ulonglong2 by = bp[1];
                unsigned long long bb[4] = { bx.x, bx.y, by.x, by.y };
                #pragma unroll
                for (int i = 0; i < 8; i++)
                    #pragma unroll
                    for (int j = 0; j < 4; j++)
                        fma2(acc[i][j], ap[i], bb[j]);
            }
            if (hasNext) {
                float* cw = cs + ((t + 1) & 1) * (DSUB * CS_STRIDE);
                cw[(dq0 + 0) * CS_STRIDE + code0 +  0] = pf0.x;
                cw[(dq0 + 1) * CS_STRIDE + code0 +  0] = pf0.y;
                cw[(dq0 + 2) * CS_STRIDE + code0 +  0] = pf0.z;
                cw[(dq0 + 3) * CS_STRIDE + code0 +  0] = pf0.w;
                cw[(dq0 + 0) * CS_STRIDE + code0 + 32] = pf1.x;
                cw[(dq0 + 1) * CS_STRIDE + code0 + 32] = pf1.y;
                cw[(dq0 + 2) * CS_STRIDE + code0 + 32] = pf1.z;
                cw[(dq0 + 3) * CS_STRIDE + code0 + 32] = pf1.w;
                cw[(dq0 + 0) * CS_STRIDE + code0 + 64] = pf2.x;
                cw[(dq0 + 1) * CS_STRIDE + code0 + 64] = pf2.y;
                cw[(dq0 + 2) * CS_STRIDE + code0 + 64] = pf2.z;
                cw[(dq0 + 3) * CS_STRIDE + code0 + 64] = pf2.w;
                cw[(dq0 + 0) * CS_STRIDE + code0 + 96] = pf3.x;
                cw[(dq0 + 1) * CS_STRIDE + code0 + 96] = pf3.y;
                cw[(dq0 + 2) * CS_STRIDE + code0 + 96] = pf3.z;
                cw[(dq0 + 3) * CS_STRIDE + code0 + 96] = pf3.w;
            }
            __syncthreads();
        }

        // ---- per-chunk argmin epilogue: score = csq[k] - 2*dot (z^2 invariant) ----
        #pragma unroll
        for (int i = 0; i < 8; i++) {
            float mv = 3.4028235e38f; int mi = 0;
            #pragma unroll
            for (int j = 0; j < 4; j++) {
                const int k0 = kc * TKC + ty * 8 + j * 2;
                float lo, hi; upk(acc[i][j], lo, hi);
                float s0 = fmaf(-2.f, lo, g_csq[k0]);
                float s1 = fmaf(-2.f, hi, g_csq[k0 + 1]);
                if (s0 < mv) { mv = s0; mi = k0; }
                if (s1 < mv) { mv = s1; mi = k0 + 1; }
                acc[i][j] = 0ull;
            }
            redv[ty * TM + tx * 8 + i] = mv;
            redi[ty * TM + tx * 8 + i] = mi;
        }
        __syncthreads();
        if (tid < TM) {
            float bv = bestv[tid]; int bi = besti[tid];
            #pragma unroll
            for (int y = 0; y < 16; y++) {
                float v = redv[y * TM + tid];
                int  ix = redi[y * TM + tid];
                if (v < bv || (v == bv && ix < bi)) { bv = v; bi = ix; }
            }
            bestv[tid] = bv; besti[tid] = bi;
        }
        __syncthreads();
    }

    // ---- gather: stage codebook rows via smem so reads AND writes coalesce ----
    // zs reused as [t][257] (padded: conflict-free transposed reads)
    for (int j = tid; j < TM * 64; j += NTHR) {
        int t  = j >> 6;
        int f4 = j & 63;
        float4 v = *(const float4*)(cb + (size_t)besti[t] * DDIM + (f4 << 2));
        float* p = zs + t * 257 + (f4 << 2);
        p[0] = v.x; p[1] = v.y; p[2] = v.z; p[3] = v.w;
    }
    __syncthreads();
    float* ob = out + ((size_t)batch * DDIM) * TLEN + t0;
    for (int i = tid; i < DDIM * TM; i += NTHR) {
        int d = i >> 7;
        int t = i & 127;
        ob[(size_t)d * TLEN + t] = zs[t * 257 + d];
    }
}

extern "C" void kernel_launch(void* const* d_in, const int* in_sizes, int n_in,
                              void* d_out, int out_size) {
    const float* z  = (const float*)d_in[0];
    const float* cb = (const float*)d_in[1];
    float* out = (float*)d_out;
    cudaFuncSetAttribute(vq_kernel, cudaFuncAttributeMaxDynamicSharedMemorySize,
                         SMEM_FLOATS * 4);
    csq_kernel<<<KCB / 8, 256>>>(cb);
    vq_kernel<<<512, NTHR, SMEM_FLOATS * 4>>>(z, cb, out);
}